// round 2
// baseline (speedup 1.0000x reference)
#include <cuda_runtime.h>
#include <cuda_bf16.h>

// Problem shape (fixed for this bench problem)
#define SEQ  1024
#define BAT  512
#define NTAG 64

// Scratch (device globals: allocation-free rule)
__device__ float g_denom[BAT];
__device__ float g_score[BAT];
__device__ int   g_maskT[BAT * SEQ];
__device__ int   g_tags_is64;

// ---------------------------------------------------------------------------
// Detect tags dtype at runtime. Reference declares int64, but JAX without x64
// downgrades to int32. If data is little-endian int64 (values < 64), every odd
// 32-bit word is zero. For int32 data, odd words are random tags in [0,64):
// P(all 64 sampled are 0) ~ 64^-64 ~ 0.
// ---------------------------------------------------------------------------
__global__ void detect_tags_kernel(const int* __restrict__ tags32) {
    int is64 = 1;
    for (int i = 1; i < 128; i += 2)
        if (tags32[i] != 0) { is64 = 0; break; }
    g_tags_is64 = is64;
}

__device__ __forceinline__ int load_tag(const void* tags, size_t idx, int is64) {
    if (is64) return (int)((const long long*)tags)[idx];
    return ((const int*)tags)[idx];
}

// ---------------------------------------------------------------------------
// Transpose mask [S,B] -> [B,S] so per-batch kernels read it contiguously.
// ---------------------------------------------------------------------------
__global__ void mask_transpose_kernel(const int* __restrict__ mask) {
    int idx = blockIdx.x * blockDim.x + threadIdx.x;
    if (idx < SEQ * BAT) {
        int t = idx / BAT;
        int b = idx - t * BAT;
        g_maskT[b * SEQ + t] = mask[idx];
    }
}

// ---------------------------------------------------------------------------
// Forward algorithm (log-denominator). One 64-thread block per batch element.
// Thread j owns alpha_j and holds exp(trans[:, j]) packed in 32 x f32x2 regs.
// Recurrence: alpha'_j = logit_j + m + log( sum_i exp(alpha_i - m) * E[i][j] )
// m = thread-0 alpha from the previous step (any shift is mathematically
// exact; exponent stays within ~[-4, 12], safe for fp32).
// ---------------------------------------------------------------------------
__global__ __launch_bounds__(NTAG) void crf_forward_kernel(
    const float* __restrict__ logits,   // [S, B, T]
    const float* __restrict__ trans,    // [T, T]
    const float* __restrict__ startt,   // [T]
    const float* __restrict__ endt)     // [T]
{
    const int b = blockIdx.x;
    const int j = threadIdx.x;  // 0..63

    // E column, packed pairs: Ep[i] = (exp(trans[2i][j]), exp(trans[2i+1][j]))
    unsigned long long Ep[NTAG / 2];
#pragma unroll
    for (int i = 0; i < NTAG / 2; i++) {
        float e0 = __expf(trans[(2 * i) * NTAG + j]);
        float e1 = __expf(trans[(2 * i + 1) * NTAG + j]);
        asm("mov.b64 %0, {%1, %2};" : "=l"(Ep[i]) : "f"(e0), "f"(e1));
    }

    // alpha0 = start + logits[0]
    float alpha = startt[j] + logits[(size_t)b * NTAG + j];

    __shared__ float se[2][NTAG];   // double-buffered exp(alpha - m)
    __shared__ float sm0[2];        // thread-0 alpha (next shift)
    __shared__ float sinit;

    if (j == 0) sinit = alpha;
    __syncthreads();
    float m = sinit;

    const int* mrow = &g_maskT[b * SEQ];

    // prefetch logits for t=1
    float logit_next = logits[((size_t)1 * BAT + b) * NTAG + j];

    for (int t = 1; t < SEQ; t++) {
        const int buf = t & 1;
        const float logit = logit_next;
        if (t + 1 < SEQ)
            logit_next = logits[((size_t)(t + 1) * BAT + b) * NTAG + j];
        const int mk = mrow[t];

        se[buf][j] = __expf(alpha - m);
        if (j == 0) sm0[buf] = alpha;
        __syncthreads();

        // 64-wide dot product in packed f32x2: v = sum_i se[i] * Ec[i]
        unsigned long long acc0 = 0ull, acc1 = 0ull;  // (0.f, 0.f) bit pattern
        const float4* s4 = (const float4*)(&se[buf][0]);
#pragma unroll
        for (int i = 0; i < NTAG / 4; i++) {
            float4 s = s4[i];
            unsigned long long p0, p1;
            asm("mov.b64 %0, {%1, %2};" : "=l"(p0) : "f"(s.x), "f"(s.y));
            asm("mov.b64 %0, {%1, %2};" : "=l"(p1) : "f"(s.z), "f"(s.w));
            asm("fma.rn.f32x2 %0, %1, %2, %0;" : "+l"(acc0) : "l"(p0), "l"(Ep[2 * i]));
            asm("fma.rn.f32x2 %0, %1, %2, %0;" : "+l"(acc1) : "l"(p1), "l"(Ep[2 * i + 1]));
        }
        float a0, a1, b0, b1;
        asm("mov.b64 {%0, %1}, %2;" : "=f"(a0), "=f"(a1) : "l"(acc0));
        asm("mov.b64 {%0, %1}, %2;" : "=f"(b0), "=f"(b1) : "l"(acc1));
        const float v = (a0 + a1) + (b0 + b1);

        const float na = logit + m + __logf(v);
        alpha = mk ? na : alpha;      // mask blend (mask is 0/1)
        m = sm0[buf];                  // shift for next step
    }

    // log_denominator = logsumexp_j(alpha_j + end_j)
    float x = alpha + endt[j];
    float mm = x;
#pragma unroll
    for (int o = 16; o > 0; o >>= 1)
        mm = fmaxf(mm, __shfl_xor_sync(0xffffffffu, mm, o));
    __shared__ float sred[2];
    if ((j & 31) == 0) sred[j >> 5] = mm;
    __syncthreads();
    mm = fmaxf(sred[0], sred[1]);

    float e = __expf(x - mm);
#pragma unroll
    for (int o = 16; o > 0; o >>= 1)
        e += __shfl_xor_sync(0xffffffffu, e, o);
    __shared__ float ssum[2];
    if ((j & 31) == 0) ssum[j >> 5] = e;
    __syncthreads();
    if (j == 0) g_denom[b] = mm + __logf(ssum[0] + ssum[1]);
}

// ---------------------------------------------------------------------------
// Numerator (gold-path score). One warp per batch element.
// ---------------------------------------------------------------------------
__global__ void crf_score_kernel(
    const float* __restrict__ logits,   // [S, B, T]
    const void* __restrict__ tags,      // [S, B] int32 or int64 (detected)
    const float* __restrict__ trans,
    const float* __restrict__ startt,
    const float* __restrict__ endt)
{
    const int gwarp = (blockIdx.x * blockDim.x + threadIdx.x) >> 5;
    const int lane = threadIdx.x & 31;
    if (gwarp >= BAT) return;
    const int b = gwarp;
    const int is64 = g_tags_is64;
    const int* mrow = &g_maskT[b * SEQ];

    float s = 0.f;
    int msum = 0;
    for (int t = lane; t < SEQ; t += 32) {
        const int tg = load_tag(tags, (size_t)t * BAT + b, is64);
        const int mt = mrow[t];
        msum += mt;
        if (t < SEQ - 1) {
            const int tgn = load_tag(tags, (size_t)(t + 1) * BAT + b, is64);
            const int mtn = mrow[t + 1];
            s += trans[tg * NTAG + tgn] * (float)mtn;
            s += logits[((size_t)t * BAT + b) * NTAG + tg] * (float)mt;
        }
    }
#pragma unroll
    for (int o = 16; o > 0; o >>= 1) {
        s += __shfl_xor_sync(0xffffffffu, s, o);
        msum += __shfl_xor_sync(0xffffffffu, msum, o);
    }
    if (lane == 0) {
        const int last_idx = msum - 1;
        const int last_tag = load_tag(tags, (size_t)last_idx * BAT + b, is64);
        const int tg0 = load_tag(tags, (size_t)b, is64);
        const float mlast = (float)mrow[SEQ - 1];
        s += startt[tg0] + endt[last_tag]
           + logits[((size_t)(SEQ - 1) * BAT + b) * NTAG + last_tag] * mlast;
        g_score[b] = s;
    }
}

// ---------------------------------------------------------------------------
// Deterministic final reduction: out = sum_b (score_b - denom_b)
// ---------------------------------------------------------------------------
__global__ void crf_reduce_kernel(float* __restrict__ out) {
    __shared__ float sm[BAT];
    const int i = threadIdx.x;
    sm[i] = g_score[i] - g_denom[i];
    __syncthreads();
    for (int o = BAT / 2; o > 0; o >>= 1) {
        if (i < o) sm[i] += sm[i + o];
        __syncthreads();
    }
    if (i == 0) out[0] = sm[0];
}

// ---------------------------------------------------------------------------
extern "C" void kernel_launch(void* const* d_in, const int* in_sizes, int n_in,
                              void* d_out, int out_size) {
    const float* logits = (const float*)d_in[0];   // [S,B,T] f32
    const void*  tags   = d_in[1];                 // [S,B] i32 or i64
    const int*   mask   = (const int*)d_in[2];     // [S,B] i32
    const float* trans  = (const float*)d_in[3];   // [T,T]
    const float* startt = (const float*)d_in[4];   // [T]
    const float* endt   = (const float*)d_in[5];   // [T]
    float* out = (float*)d_out;

    detect_tags_kernel<<<1, 1>>>((const int*)tags);
    mask_transpose_kernel<<<(SEQ * BAT + 255) / 256, 256>>>(mask);
    crf_forward_kernel<<<BAT, NTAG>>>(logits, trans, startt, endt);
    crf_score_kernel<<<BAT / 4, 128>>>(logits, tags, trans, startt, endt);
    crf_reduce_kernel<<<1, BAT>>>(out);
}

// round 3
// speedup vs baseline: 3.3739x; 3.3739x over previous
#include <cuda_runtime.h>
#include <cuda_bf16.h>

// Problem shape (fixed for this bench problem)
#define SEQ  1024
#define BAT  512
#define NTAG 64
#define TSTRIDE (BAT * NTAG)

// Scratch (device globals: allocation-free rule)
__device__ float g_denom[BAT];
__device__ float g_score[BAT];
__device__ int   g_maskT[BAT * SEQ];
__device__ int   g_tags_is64;
__device__ int   g_mask_ones;

// ---------------------------------------------------------------------------
// Detect tags dtype (int64 vs JAX-downgraded int32) and reset the mask flag.
// ---------------------------------------------------------------------------
__global__ void detect_tags_kernel(const int* __restrict__ tags32) {
    int is64 = 1;
    for (int i = 1; i < 128; i += 2)
        if (tags32[i] != 0) { is64 = 0; break; }
    g_tags_is64 = is64;
    g_mask_ones = 1;
}

__device__ __forceinline__ int load_tag(const void* tags, size_t idx, int is64) {
    if (is64) return (int)((const long long*)tags)[idx];
    return ((const int*)tags)[idx];
}

// ---------------------------------------------------------------------------
// Transpose mask [S,B] -> [B,S]; also detect "all ones" (fast-path trigger).
// ---------------------------------------------------------------------------
__global__ void mask_transpose_kernel(const int* __restrict__ mask) {
    int idx = blockIdx.x * blockDim.x + threadIdx.x;
    if (idx < SEQ * BAT) {
        int t = idx / BAT;
        int b = idx - t * BAT;
        int v = mask[idx];
        g_maskT[b * SEQ + t] = v;
        if (v != 1) g_mask_ones = 0;   // benign race: all writers store 0
    }
}

// ---------------------------------------------------------------------------
// One linear-space forward step (mask == all ones fast path).
// Invariant: alpha_j = m0 + e_sum*ln2 + log(s_j), s in shared (prev buffer).
// ---------------------------------------------------------------------------
__device__ __forceinline__ float fast_step(
    const float* __restrict__ se_read, float* __restrict__ se_write, int j,
    const unsigned long long* __restrict__ Ep, float rawv, int& e_sum)
{
    const float c = __expf(rawv);   // MUFU hidden under the dot below

    // renorm scale from broadcast s_0 (exact power of 2) — off critical path
    const float s0 = se_read[0];
    int ex = (__float_as_int(s0) >> 23) & 0xFF;
    ex = max(1, min(ex, 253));
    e_sum += ex - 127;
    const float rsc = __int_as_float((254 - ex) << 23);  // 2^(127-(ex-127))

    // 64-wide dot in packed f32x2, 4 accumulators (chain depth 8)
    unsigned long long a0 = 0ull, a1 = 0ull, a2 = 0ull, a3 = 0ull;
    const float4* s4 = (const float4*)se_read;
#pragma unroll
    for (int i = 0; i < 16; i += 2) {
        float4 sA = s4[i];
        float4 sB = s4[i + 1];
        unsigned long long p0, p1, p2, p3;
        asm("mov.b64 %0, {%1, %2};" : "=l"(p0) : "f"(sA.x), "f"(sA.y));
        asm("mov.b64 %0, {%1, %2};" : "=l"(p1) : "f"(sA.z), "f"(sA.w));
        asm("mov.b64 %0, {%1, %2};" : "=l"(p2) : "f"(sB.x), "f"(sB.y));
        asm("mov.b64 %0, {%1, %2};" : "=l"(p3) : "f"(sB.z), "f"(sB.w));
        asm("fma.rn.f32x2 %0, %1, %2, %0;" : "+l"(a0) : "l"(p0), "l"(Ep[2 * i + 0]));
        asm("fma.rn.f32x2 %0, %1, %2, %0;" : "+l"(a1) : "l"(p1), "l"(Ep[2 * i + 1]));
        asm("fma.rn.f32x2 %0, %1, %2, %0;" : "+l"(a2) : "l"(p2), "l"(Ep[2 * i + 2]));
        asm("fma.rn.f32x2 %0, %1, %2, %0;" : "+l"(a3) : "l"(p3), "l"(Ep[2 * i + 3]));
    }
    asm("add.rn.f32x2 %0, %0, %1;" : "+l"(a0) : "l"(a2));
    asm("add.rn.f32x2 %0, %0, %1;" : "+l"(a1) : "l"(a3));
    asm("add.rn.f32x2 %0, %0, %1;" : "+l"(a0) : "l"(a1));
    float lo, hi;
    asm("mov.b64 {%0, %1}, %2;" : "=f"(lo), "=f"(hi) : "l"(a0));
    const float v = lo + hi;

    const float snew = v * c * rsc;
    se_write[j] = snew;
    __syncthreads();
    return snew;
}

// ---------------------------------------------------------------------------
// Forward algorithm (log-denominator). One 64-thread block per batch element.
// Thread j owns column j; exp(trans[:,j]) lives packed in 32 f32x2 registers.
// ---------------------------------------------------------------------------
__global__ __launch_bounds__(NTAG) void crf_forward_kernel(
    const float* __restrict__ logits,   // [S, B, T]
    const float* __restrict__ trans,    // [T, T]
    const float* __restrict__ startt,   // [T]
    const float* __restrict__ endt)     // [T]
{
    const int b = blockIdx.x;
    const int j = threadIdx.x;  // 0..63

    // E column, packed pairs: Ep[i] = (exp(trans[2i][j]), exp(trans[2i+1][j]))
    unsigned long long Ep[NTAG / 2];
#pragma unroll
    for (int i = 0; i < NTAG / 2; i++) {
        float e0 = __expf(trans[(2 * i) * NTAG + j]);
        float e1 = __expf(trans[(2 * i + 1) * NTAG + j]);
        asm("mov.b64 %0, {%1, %2};" : "=l"(Ep[i]) : "f"(e0), "f"(e1));
    }

    __shared__ float se[2][NTAG];
    __shared__ float sh_aux[2];

    const float alpha0 = startt[j] + logits[(size_t)b * NTAG + j];
    if (j == 0) sh_aux[0] = alpha0;
    __syncthreads();
    const float m0 = sh_aux[0];

    const float* lptr = logits + (size_t)b * NTAG + j;

    if (g_mask_ones) {
        // ============== FAST PATH: pure linear-space recurrence ==============
        float sj = __expf(alpha0 - m0);
        se[0][j] = sj;
        __syncthreads();

        // prefetch ring, depth 8
        float raw[8];
#pragma unroll
        for (int u = 0; u < 8; u++)
            raw[u] = lptr[(size_t)(1 + u) * TSTRIDE];

        int e_sum = 0;
        int t0;
        for (t0 = 1; t0 + 7 <= SEQ - 1; t0 += 8) {
#pragma unroll
            for (int u = 0; u < 8; u++) {
                sj = fast_step(se[u & 1], se[(u & 1) ^ 1], j, Ep, raw[u], e_sum);
                if (t0 + u + 8 <= SEQ - 1)
                    raw[u] = lptr[(size_t)(t0 + u + 8) * TSTRIDE];
            }
        }
        // remainder steps (SEQ-1 = 1023 = 127*8 + 7): t = 1017..1023
#pragma unroll
        for (int u = 0; u < 7; u++)
            sj = fast_step(se[u & 1], se[(u & 1) ^ 1], j, Ep, raw[u], e_sum);

        // final logsumexp over j of (alpha_j + end_j)
        float x = m0 + (float)e_sum * 0.69314718055994531f + logf(sj) + endt[j];
        float mm = x;
#pragma unroll
        for (int o = 16; o > 0; o >>= 1)
            mm = fmaxf(mm, __shfl_xor_sync(0xffffffffu, mm, o));
        if ((j & 31) == 0) sh_aux[j >> 5] = mm;
        __syncthreads();
        mm = fmaxf(sh_aux[0], sh_aux[1]);
        float e = __expf(x - mm);
#pragma unroll
        for (int o = 16; o > 0; o >>= 1)
            e += __shfl_xor_sync(0xffffffffu, e, o);
        __syncthreads();
        if ((j & 31) == 0) sh_aux[j >> 5] = e;
        __syncthreads();
        if (j == 0) g_denom[b] = mm + logf(sh_aux[0] + sh_aux[1]);
        return;
    }

    // ============== GENERAL PATH: log-space with mask blend ==============
    {
        __shared__ float sm0[2];
        float alpha = alpha0;
        float m = m0;
        const int* mrow = &g_maskT[b * SEQ];
        float logit_next = lptr[(size_t)1 * TSTRIDE];

        for (int t = 1; t < SEQ; t++) {
            const int buf = t & 1;
            const float logit = logit_next;
            if (t + 1 < SEQ) logit_next = lptr[(size_t)(t + 1) * TSTRIDE];
            const int mk = mrow[t];

            se[buf][j] = __expf(alpha - m);
            if (j == 0) sm0[buf] = alpha;
            __syncthreads();

            unsigned long long acc0 = 0ull, acc1 = 0ull;
            const float4* s4 = (const float4*)(&se[buf][0]);
#pragma unroll
            for (int i = 0; i < NTAG / 4; i++) {
                float4 s = s4[i];
                unsigned long long p0, p1;
                asm("mov.b64 %0, {%1, %2};" : "=l"(p0) : "f"(s.x), "f"(s.y));
                asm("mov.b64 %0, {%1, %2};" : "=l"(p1) : "f"(s.z), "f"(s.w));
                asm("fma.rn.f32x2 %0, %1, %2, %0;" : "+l"(acc0) : "l"(p0), "l"(Ep[2 * i]));
                asm("fma.rn.f32x2 %0, %1, %2, %0;" : "+l"(acc1) : "l"(p1), "l"(Ep[2 * i + 1]));
            }
            float a0, a1, b0, b1;
            asm("mov.b64 {%0, %1}, %2;" : "=f"(a0), "=f"(a1) : "l"(acc0));
            asm("mov.b64 {%0, %1}, %2;" : "=f"(b0), "=f"(b1) : "l"(acc1));
            const float v = (a0 + a1) + (b0 + b1);

            const float na = logit + m + __logf(v);
            alpha = mk ? na : alpha;
            m = sm0[buf];
            __syncthreads();
        }

        float x = alpha + endt[j];
        float mm = x;
#pragma unroll
        for (int o = 16; o > 0; o >>= 1)
            mm = fmaxf(mm, __shfl_xor_sync(0xffffffffu, mm, o));
        if ((j & 31) == 0) sh_aux[j >> 5] = mm;
        __syncthreads();
        mm = fmaxf(sh_aux[0], sh_aux[1]);
        float e = __expf(x - mm);
#pragma unroll
        for (int o = 16; o > 0; o >>= 1)
            e += __shfl_xor_sync(0xffffffffu, e, o);
        __syncthreads();
        if ((j & 31) == 0) sh_aux[j >> 5] = e;
        __syncthreads();
        if (j == 0) g_denom[b] = mm + logf(sh_aux[0] + sh_aux[1]);
    }
}

// ---------------------------------------------------------------------------
// Numerator (gold-path score). One 128-thread block per batch element.
// ---------------------------------------------------------------------------
__global__ __launch_bounds__(128) void crf_score_kernel(
    const float* __restrict__ logits,   // [S, B, T]
    const void* __restrict__ tags,      // [S, B] int32 or int64 (detected)
    const float* __restrict__ trans,
    const float* __restrict__ startt,
    const float* __restrict__ endt)
{
    const int b = blockIdx.x;
    const int tid = threadIdx.x;   // 0..127
    const int is64 = g_tags_is64;
    const int* mrow = &g_maskT[b * SEQ];

    float s = 0.f;
    int msum = 0;
    for (int t = tid; t < SEQ; t += 128) {
        const int tg = load_tag(tags, (size_t)t * BAT + b, is64);
        const int mt = mrow[t];
        msum += mt;
        if (t < SEQ - 1) {
            const int tgn = load_tag(tags, (size_t)(t + 1) * BAT + b, is64);
            const int mtn = mrow[t + 1];
            s += trans[tg * NTAG + tgn] * (float)mtn;
            s += logits[((size_t)t * BAT + b) * NTAG + tg] * (float)mt;
        }
    }

    __shared__ float ss[128];
    __shared__ int   sm[128];
    ss[tid] = s;
    sm[tid] = msum;
    __syncthreads();
    for (int o = 64; o > 0; o >>= 1) {
        if (tid < o) { ss[tid] += ss[tid + o]; sm[tid] += sm[tid + o]; }
        __syncthreads();
    }

    if (tid == 0) {
        const int last_idx = sm[0] - 1;
        const int last_tag = load_tag(tags, (size_t)last_idx * BAT + b, is64);
        const int tg0 = load_tag(tags, (size_t)b, is64);
        const float mlast = (float)mrow[SEQ - 1];
        g_score[b] = ss[0] + startt[tg0] + endt[last_tag]
                   + logits[((size_t)(SEQ - 1) * BAT + b) * NTAG + last_tag] * mlast;
    }
}

// ---------------------------------------------------------------------------
// Deterministic final reduction: out = sum_b (score_b - denom_b)
// ---------------------------------------------------------------------------
__global__ void crf_reduce_kernel(float* __restrict__ out) {
    __shared__ float sm[BAT];
    const int i = threadIdx.x;
    sm[i] = g_score[i] - g_denom[i];
    __syncthreads();
    for (int o = BAT / 2; o > 0; o >>= 1) {
        if (i < o) sm[i] += sm[i + o];
        __syncthreads();
    }
    if (i == 0) out[0] = sm[0];
}

// ---------------------------------------------------------------------------
extern "C" void kernel_launch(void* const* d_in, const int* in_sizes, int n_in,
                              void* d_out, int out_size) {
    const float* logits = (const float*)d_in[0];   // [S,B,T] f32
    const void*  tags   = d_in[1];                 // [S,B] i32 or i64
    const int*   mask   = (const int*)d_in[2];     // [S,B] i32
    const float* trans  = (const float*)d_in[3];   // [T,T]
    const float* startt = (const float*)d_in[4];   // [T]
    const float* endt   = (const float*)d_in[5];   // [T]
    float* out = (float*)d_out;

    detect_tags_kernel<<<1, 1>>>((const int*)tags);
    mask_transpose_kernel<<<(SEQ * BAT + 255) / 256, 256>>>(mask);
    crf_forward_kernel<<<BAT, NTAG>>>(logits, trans, startt, endt);
    crf_score_kernel<<<BAT, 128>>>(logits, tags, trans, startt, endt);
    crf_reduce_kernel<<<1, BAT>>>(out);
}